// round 5
// baseline (speedup 1.0000x reference)
#include <cuda_runtime.h>
#include <math.h>
#include <stdint.h>

// Problem constants
#define NN   25600          // nodes
#define EE   409600         // edges
#define GG   128            // graphs
#define INF_ 200            // raw feature dim
#define IN2  400            // 2*IN after nan-mask concat
#define HC4  256            // H*C for layers 0/1
#define ETOT (EE + NN)      // edges + self loops

#define NEG_BIG (-1.0e30f)  // finite "-inf" so online-softmax combine never does inf-inf

// ---------------- scratch (device globals; no allocation allowed) ----------------
__device__ __align__(16) float d_h   [(size_t)NN * HC4];     // GEMM output / attn input
__device__ __align__(16) float d_xn  [(size_t)NN * HC4];     // next-layer input
__device__ __align__(16) float d_o2  [(size_t)NN * 64];      // layer-2 node output
__device__ __align__(16) float d_asb[NN * 4];
__device__ __align__(16) float d_adb[NN * 4];
__device__ int   d_cnt[NN];
__device__ int   d_fill[NN];
__device__ float d_easum[NN];
__device__ int   d_rowptr[NN + 1];
__device__ int   d_csrc[ETOT];
__device__ float d_cea [ETOT];
__device__ float d_gsum[GG * 64];
__device__ float d_gcnt[GG];
__device__ float d_wd[9];   // we_dot: layer0 heads 0..3, layer1 heads 4..7, layer2 at 8

// ---------------- helpers ----------------
__device__ __forceinline__ float warp_sum(float v) {
    #pragma unroll
    for (int o = 16; o; o >>= 1) v += __shfl_xor_sync(0xffffffffu, v, o);
    return v;
}
// packed fp32x2 FMA (Blackwell FFMA2 — only reachable via PTX)
__device__ __forceinline__ void ffma2(uint64_t& d, uint64_t a, uint64_t b) {
    asm("fma.rn.f32x2 %0, %1, %2, %0;" : "+l"(d) : "l"(a), "l"(b));
}
__device__ __forceinline__ float2 unpk(uint64_t v) {
    float2 r; asm("mov.b64 {%0, %1}, %2;" : "=f"(r.x), "=f"(r.y) : "l"(v)); return r;
}

// ---------------- zero scratch counters ----------------
__global__ void zero_kernel() {
    int i = blockIdx.x * blockDim.x + threadIdx.x;
    if (i < NN) { d_cnt[i] = 0; d_fill[i] = 0; d_easum[i] = 0.f; }
    if (i < GG * 64) d_gsum[i] = 0.f;
    if (i < GG) d_gcnt[i] = 0.f;
}

// ---------------- CSR build ----------------
__global__ void count_kernel(const int* __restrict__ ei, const float* __restrict__ ea) {
    int e = blockIdx.x * blockDim.x + threadIdx.x;
    if (e >= EE) return;
    int d = ei[EE + e];
    float v = ea[e];
    if (v != v) v = 0.f;              // nan_to_num
    atomicAdd(&d_cnt[d], 1);
    atomicAdd(&d_easum[d], v);
}

// single-block exclusive scan of (cnt[n]+1) -> rowptr, warp-shuffle based
__global__ void scan_kernel() {
    __shared__ int wsum[32];
    __shared__ int s_off;
    int tid = threadIdx.x, lane = tid & 31, wid = tid >> 5;
    if (tid == 0) { d_rowptr[0] = 0; s_off = 0; }
    __syncthreads();
    for (int base = 0; base < NN; base += 1024) {
        int v = d_cnt[base + tid] + 1;    // +1 for the self loop
        int inc = v;
        #pragma unroll
        for (int o = 1; o < 32; o <<= 1) {
            int t = __shfl_up_sync(0xffffffffu, inc, o);
            if (lane >= o) inc += t;
        }
        if (lane == 31) wsum[wid] = inc;
        __syncthreads();
        if (wid == 0) {
            int wi = wsum[lane];
            #pragma unroll
            for (int o = 1; o < 32; o <<= 1) {
                int t = __shfl_up_sync(0xffffffffu, wi, o);
                if (lane >= o) wi += t;
            }
            wsum[lane] = wi;              // inclusive warp sums
        }
        __syncthreads();
        int excl_w = wid ? wsum[wid - 1] : 0;
        d_rowptr[base + tid + 1] = s_off + excl_w + inc;
        __syncthreads();
        if (tid == 0) s_off += wsum[31];
        __syncthreads();
    }
}

__global__ void fill_kernel(const int* __restrict__ ei, const float* __restrict__ ea) {
    int e = blockIdx.x * blockDim.x + threadIdx.x;
    if (e >= EE) return;
    int s = ei[e], d = ei[EE + e];
    float v = ea[e];
    if (v != v) v = 0.f;
    int pos = d_rowptr[d] + atomicAdd(&d_fill[d], 1);
    d_csrc[pos] = s;
    d_cea[pos]  = v;
}

__global__ void selfloop_kernel() {
    int n = blockIdx.x * blockDim.x + threadIdx.x;
    if (n >= NN) return;
    int pos = d_rowptr[n + 1] - 1;    // self loop occupies the last slot of the row
    d_csrc[pos] = n;
    d_cea[pos]  = d_easum[n] / fmaxf((float)d_cnt[n], 1.f);
}

// ---------------- we_dot[h] = dot(We row of head h, ae[h]) ----------------
__global__ void wd_kernel(const float* We0, const float* ae0,
                          const float* We1, const float* ae1,
                          const float* We2, const float* ae2) {
    int w = threadIdx.x >> 5, lane = threadIdx.x & 31;
    if (w >= 9) return;
    const float *We, *ae; int h;
    if (w < 4)      { We = We0; ae = ae0; h = w; }
    else if (w < 8) { We = We1; ae = ae1; h = w - 4; }
    else            { We = We2; ae = ae2; h = 0; }
    float s = 0.f;
    for (int c = lane; c < 64; c += 32) s += We[h * 64 + c] * ae[h * 64 + c];
    s = warp_sum(s);
    if (lane == 0) d_wd[w] = s;
}

// ---------------- f32x2 GEMM: d_h = A @ B, A row-major [25600,K], B [K,Nn] ----------------
// XF=1: A synthesized from raw x: A[m,k] = k<200 ? nan2num(x[m,k]) : isnan(x[m,k-200]).
// Tile BM x BN, T threads, 4x8 per thread. B stored DUPLICATED in smem
// (each value twice, i-interleaved) so the inner loop is pure LDS.128 + FFMA2
// with no dup-MOVs and conflict-free B reads.
template <int BM, int BN, int T, int XF, int OCC>
__global__ __launch_bounds__(T, OCC) void gemm3_kernel(const float* __restrict__ Xin,
                                                       const float* __restrict__ B,
                                                       int Nn, int K) {
    const float* __restrict__ A = d_xn;
    constexpr int TX = BN / 8;              // threads across N
    constexpr int AV = (BM * 16) / (4 * T); // A float4 loads per thread per tile
    constexpr int BV = (BN * 16) / (4 * T); // B float4 loads per thread per tile
    constexpr int BN4 = BN / 4;
    constexpr int BMP = BM + 4;

    __shared__ __align__(16) float As[2][16][BMP];
    __shared__ __align__(16) float Bs[2][16][2 * BN];   // duplicated B

    int tid = threadIdx.x;
    int tx  = tid % TX;
    int ty4 = (tid / TX) * 4;
    int m0 = blockIdx.y * BM, n0 = blockIdx.x * BN;

    uint64_t acc[2][8];
    #pragma unroll
    for (int r = 0; r < 2; r++)
        #pragma unroll
        for (int j = 0; j < 8; j++) acc[r][j] = 0ull;

    float4 pa[AV], pb[BV];
    int arow[AV], ac[AV], brow[BV], bc[BV];
    #pragma unroll
    for (int i = 0; i < AV; i++) { int idx = tid + i * T; arow[i] = idx >> 2; ac[i] = idx & 3; }
    #pragma unroll
    for (int i = 0; i < BV; i++) { int idx = tid + i * T; brow[i] = idx / BN4; bc[i] = idx % BN4; }

    int ktiles = K >> 4;

    auto loadA = [&](int i, int k0) -> float4 {
        int m = m0 + arow[i];
        int kk = k0 + ac[i] * 4;
        if (XF) {
            int c = (kk < INF_) ? kk : (kk - INF_);
            float4 v = *(const float4*)&Xin[(size_t)m * INF_ + c];
            float4 r;
            bool lo = (kk < INF_);
            r.x = (v.x != v.x) ? (lo ? 0.f : 1.f) : (lo ? v.x : 0.f);
            r.y = (v.y != v.y) ? (lo ? 0.f : 1.f) : (lo ? v.y : 0.f);
            r.z = (v.z != v.z) ? (lo ? 0.f : 1.f) : (lo ? v.z : 0.f);
            r.w = (v.w != v.w) ? (lo ? 0.f : 1.f) : (lo ? v.w : 0.f);
            return r;
        } else {
            return *(const float4*)&A[(size_t)m * K + kk];
        }
    };
    auto storeTile = [&](int b) {
        #pragma unroll
        for (int i = 0; i < AV; i++) {
            As[b][ac[i] * 4 + 0][arow[i]] = pa[i].x;
            As[b][ac[i] * 4 + 1][arow[i]] = pa[i].y;
            As[b][ac[i] * 4 + 2][arow[i]] = pa[i].z;
            As[b][ac[i] * 4 + 3][arow[i]] = pa[i].w;
        }
        #pragma unroll
        for (int i = 0; i < BV; i++) {
            int c0 = bc[i] * 4;
            int i0 = (c0 & 7) >> 1;       // 0 or 2
            int ts = c0 >> 3;
            float* base = &Bs[b][brow[i]][0];
            *(float4*)&base[(i0 * TX + ts) * 4]       = make_float4(pb[i].x, pb[i].x, pb[i].y, pb[i].y);
            *(float4*)&base[((i0 + 1) * TX + ts) * 4] = make_float4(pb[i].z, pb[i].z, pb[i].w, pb[i].w);
        }
    };

    // preload tile 0
    #pragma unroll
    for (int i = 0; i < AV; i++) pa[i] = loadA(i, 0);
    #pragma unroll
    for (int i = 0; i < BV; i++)
        pb[i] = *(const float4*)&B[(size_t)brow[i] * Nn + n0 + bc[i] * 4];
    storeTile(0);
    __syncthreads();

    for (int t = 0; t < ktiles; t++) {
        int buf = t & 1;
        if (t + 1 < ktiles) {
            int k0 = (t + 1) << 4;
            #pragma unroll
            for (int i = 0; i < AV; i++) pa[i] = loadA(i, k0);
            #pragma unroll
            for (int i = 0; i < BV; i++)
                pb[i] = *(const float4*)&B[(size_t)(k0 + brow[i]) * Nn + n0 + bc[i] * 4];
        }
        #pragma unroll
        for (int k = 0; k < 16; k++) {
            ulonglong2 av = *(const ulonglong2*)&As[buf][k][ty4];
            #pragma unroll
            for (int i = 0; i < 4; i++) {
                ulonglong2 bv = *(const ulonglong2*)&Bs[buf][k][(i * TX + tx) * 4];
                ffma2(acc[0][2 * i],     av.x, bv.x);
                ffma2(acc[0][2 * i + 1], av.x, bv.y);
                ffma2(acc[1][2 * i],     av.y, bv.x);
                ffma2(acc[1][2 * i + 1], av.y, bv.y);
            }
        }
        if (t + 1 < ktiles) storeTile(buf ^ 1);
        __syncthreads();
    }

    // epilogue: acc[r][j] = rows (ty4+2r, ty4+2r+1), col tx*8+j
    #pragma unroll
    for (int r = 0; r < 2; r++) {
        float2 u[8];
        #pragma unroll
        for (int j = 0; j < 8; j++) u[j] = unpk(acc[r][j]);
        size_t r0 = (size_t)(m0 + ty4 + 2 * r) * Nn + n0 + tx * 8;
        size_t r1 = r0 + Nn;
        *(float4*)&d_h[r0]     = make_float4(u[0].x, u[1].x, u[2].x, u[3].x);
        *(float4*)&d_h[r0 + 4] = make_float4(u[4].x, u[5].x, u[6].x, u[7].x);
        *(float4*)&d_h[r1]     = make_float4(u[0].y, u[1].y, u[2].y, u[3].y);
        *(float4*)&d_h[r1 + 4] = make_float4(u[4].y, u[5].y, u[6].y, u[7].y);
    }
}

// ---------------- per-node attention scalars a_s, a_d (8 warps / block) ----------------
template <int H>
__global__ __launch_bounds__(256) void attn_kernel(const float* __restrict__ att_s,
                                                   const float* __restrict__ att_d) {
    constexpr int NPB = 8 / H;
    int tid = threadIdx.x, wid = tid >> 5, lane = tid & 31;
    int n = blockIdx.x * NPB + wid / H;
    int h = wid % H;
    const float2* hr  = (const float2*)(d_h + (size_t)n * (H * 64) + h * 64);
    const float2* asv = (const float2*)(att_s + h * 64);
    const float2* adv = (const float2*)(att_d + h * 64);
    float2 hv = hr[lane], sv = asv[lane], dv = adv[lane];
    float s  = hv.x * sv.x + hv.y * sv.y;
    float dd = hv.x * dv.x + hv.y * dv.y;
    s = warp_sum(s); dd = warp_sum(dd);
    if (lane == 0) { d_asb[n * H + h] = s; d_adb[n * H + h] = dd; }
}

// ---------------- segment softmax + aggregation: one warp per dst node ----------------
template <int H>
__global__ __launch_bounds__(256) void agg_kernel(const float* __restrict__ bias,
                           const float* __restrict__ bng, const float* __restrict__ bnb,
                           const float* __restrict__ bnm, const float* __restrict__ bnv,
                           int wd_off, int do_bn, int out_sel) {
    __shared__ int   s_src[8][32];
    __shared__ float s_wt[8][32][H];

    int gw = (blockIdx.x * blockDim.x + threadIdx.x) >> 5;
    if (gw >= NN) return;
    int lane = threadIdx.x & 31;
    int wwarp = threadIdx.x >> 5;
    int n = gw;
    int beg = d_rowptr[n], end = d_rowptr[n + 1];

    float adh[H], wdv[H];
    #pragma unroll
    for (int h = 0; h < H; h++) { adh[h] = d_adb[n * H + h]; wdv[h] = d_wd[wd_off + h]; }

    // single-pass online softmax statistics (max + sum), lane-strided.
    // mx starts at a finite NEG_BIG so the combine never computes (-inf) - (-inf).
    float mx[H], sm[H];
    #pragma unroll
    for (int h = 0; h < H; h++) { mx[h] = NEG_BIG; sm[h] = 0.f; }
    for (int e = beg + lane; e < end; e += 32) {
        int s = d_csrc[e]; float ev = d_cea[e];
        float av[H];
        if constexpr (H == 4) {
            float4 a4 = *(const float4*)&d_asb[s * 4];
            av[0] = a4.x; av[1] = a4.y; av[2] = a4.z; av[3] = a4.w;
        } else {
            av[0] = d_asb[s];
        }
        #pragma unroll
        for (int h = 0; h < H; h++) {
            float t = av[h] + adh[h] + ev * wdv[h];
            t = t > 0.f ? t : 0.2f * t;
            float mn = fmaxf(mx[h], t);
            sm[h] = sm[h] * __expf(mx[h] - mn) + __expf(t - mn);
            mx[h] = mn;
        }
    }
    // warp combine of (mx, sm) — all operands finite
    #pragma unroll
    for (int h = 0; h < H; h++) {
        #pragma unroll
        for (int o = 16; o; o >>= 1) {
            float mo = __shfl_xor_sync(0xffffffffu, mx[h], o);
            float so = __shfl_xor_sync(0xffffffffu, sm[h], o);
            float mn = fmaxf(mx[h], mo);
            sm[h] = sm[h] * __expf(mx[h] - mn) + so * __expf(mo - mn);
            mx[h] = mn;
        }
    }

    // gather pass: each lane owns PL consecutive channels
    constexpr int PL = (H * 64) / 32;     // 8 (H=4) or 2 (H=1)
    int hl = (lane * PL) >> 6;            // head of this lane's channels
    float acc[PL];
    #pragma unroll
    for (int j = 0; j < PL; j++) acc[j] = 0.f;

    for (int ec = beg; ec < end; ec += 32) {
        int e = ec + lane;
        if (e < end) {
            int s = d_csrc[e]; float ev = d_cea[e];
            s_src[wwarp][lane] = s;
            float av[H];
            if constexpr (H == 4) {
                float4 a4 = *(const float4*)&d_asb[s * 4];
                av[0] = a4.x; av[1] = a4.y; av[2] = a4.z; av[3] = a4.w;
            } else {
                av[0] = d_asb[s];
            }
            #pragma unroll
            for (int h = 0; h < H; h++) {
                float t = av[h] + adh[h] + ev * wdv[h];
                t = t > 0.f ? t : 0.2f * t;
                s_wt[wwarp][lane][h] = __expf(t - mx[h]);
            }
        }
        __syncwarp();
        int cnt = min(32, end - ec);
        #pragma unroll 4
        for (int i = 0; i < cnt; i++) {
            int s = s_src[wwarp][i];
            float w = s_wt[wwarp][i][hl];
            const float* hr = d_h + (size_t)s * (H * 64) + lane * PL;
            if constexpr (PL == 8) {
                float4 v0 = *(const float4*)hr;
                float4 v1 = *(const float4*)(hr + 4);
                acc[0] = fmaf(w, v0.x, acc[0]); acc[1] = fmaf(w, v0.y, acc[1]);
                acc[2] = fmaf(w, v0.z, acc[2]); acc[3] = fmaf(w, v0.w, acc[3]);
                acc[4] = fmaf(w, v1.x, acc[4]); acc[5] = fmaf(w, v1.y, acc[5]);
                acc[6] = fmaf(w, v1.z, acc[6]); acc[7] = fmaf(w, v1.w, acc[7]);
            } else {
                float2 v = *(const float2*)hr;
                acc[0] = fmaf(w, v.x, acc[0]);
                acc[1] = fmaf(w, v.y, acc[1]);
            }
        }
        __syncwarp();
    }

    float invl = 1.f / (sm[hl] + 1e-16f);
    float* ob = out_sel ? d_o2 : d_xn;
    #pragma unroll
    for (int j = 0; j < PL; j++) {
        int c = lane * PL + j;
        float v = acc[j] * invl + bias[c];
        if (do_bn) {
            v = (v - bnm[c]) * rsqrtf(bnv[c] + 1e-5f) * bng[c] + bnb[c];
            v = fmaxf(v, 0.f);
        }
        ob[(size_t)n * (H * 64) + c] = v;
    }
}

// ---------------- global mean pool accumulation ----------------
__global__ __launch_bounds__(256) void pool_kernel(const int* __restrict__ batch) {
    int t = blockIdx.x * blockDim.x + threadIdx.x;
    int n = t >> 6, c = t & 63;
    if (n >= NN) return;
    int b = batch[n];
    atomicAdd(&d_gsum[b * 64 + c], d_o2[(size_t)n * 64 + c]);
    if (c == 0) atomicAdd(&d_gcnt[b], 1.f);
}

// ---------------- MLP head: GELU(g@cw1+cb1)@cw2+cb2 ----------------
__global__ void head_kernel(const float* __restrict__ cw1, const float* __restrict__ cb1,
                            const float* __restrict__ cw2, const float* __restrict__ cb2,
                            float* __restrict__ out) {
    int g = blockIdx.x, j = threadIdx.x;   // 64 threads
    __shared__ float sg[64], sh[64];
    float cntv = fmaxf(d_gcnt[g], 1.f);
    sg[j] = d_gsum[g * 64 + j] / cntv;
    __syncthreads();
    float a = cb1[j];
    #pragma unroll
    for (int k = 0; k < 64; k++) a = fmaf(sg[k], cw1[k * 64 + j], a);
    sh[j] = 0.5f * a * (1.f + erff(a * 0.70710678118654752440f));   // exact GELU
    __syncthreads();
    if (j < 2) {
        float o = cb2[j];
        #pragma unroll
        for (int k = 0; k < 64; k++) o = fmaf(sh[k], cw2[k * 2 + j], o);
        out[g * 2 + j] = o;
    }
}

// ---------------- launch ----------------
extern "C" void kernel_launch(void* const* d_in, const int* in_sizes, int n_in,
                              void* d_out, int out_size) {
    (void)in_sizes; (void)n_in; (void)out_size;
    const float* x     = (const float*)d_in[0];
    const int*   ei    = (const int*)  d_in[1];
    const float* ea    = (const float*)d_in[2];
    const int*   batch = (const int*)  d_in[3];
    const float* W0  = (const float*)d_in[4];
    const float* as0 = (const float*)d_in[5];
    const float* ad0 = (const float*)d_in[6];
    const float* We0 = (const float*)d_in[7];
    const float* ae0 = (const float*)d_in[8];
    const float* b0  = (const float*)d_in[9];
    const float* W1  = (const float*)d_in[10];
    const float* as1 = (const float*)d_in[11];
    const float* ad1 = (const float*)d_in[12];
    const float* We1 = (const float*)d_in[13];
    const float* ae1 = (const float*)d_in[14];
    const float* b1  = (const float*)d_in[15];
    const float* W2  = (const float*)d_in[16];
    const float* as2 = (const float*)d_in[17];
    const float* ad2 = (const float*)d_in[18];
    const float* We2 = (const float*)d_in[19];
    const float* ae2 = (const float*)d_in[20];
    const float* b2  = (const float*)d_in[21];
    const float* bng = (const float*)d_in[22];
    const float* bnb = (const float*)d_in[23];
    const float* bnm = (const float*)d_in[24];
    const float* bnv = (const float*)d_in[25];
    const float* cw1 = (const float*)d_in[26];
    const float* cb1 = (const float*)d_in[27];
    const float* cw2 = (const float*)d_in[28];
    const float* cb2 = (const float*)d_in[29];
    float* out = (float*)d_out;

    // prep + layer-0 GEMM placed 4th so the ncu window lands on it
    zero_kernel<<<100, 256>>>();
    count_kernel<<<EE / 256, 256>>>(ei, ea);
    scan_kernel<<<1, 1024>>>();
    gemm3_kernel<64, 128, 256, 1, 3><<<dim3(2, 400), 256>>>(x, W0, 256, 400);   // layer 0 GEMM
    fill_kernel<<<EE / 256, 256>>>(ei, ea);
    selfloop_kernel<<<100, 256>>>();
    wd_kernel<<<1, 288>>>(We0, ae0, We1, ae1, We2, ae2);

    // layer 0: attention + aggregation + BN + ReLU
    attn_kernel<4><<<NN / 2, 256>>>(as0, ad0);
    agg_kernel<4><<<NN / 8, 256>>>(b0, bng, bnb, bnm, bnv, 0, 1, 0);

    // layer 1: GAT(256 -> 4x64) + BN + ReLU
    gemm3_kernel<64, 128, 256, 0, 3><<<dim3(2, 400), 256>>>(nullptr, W1, 256, 256);
    attn_kernel<4><<<NN / 2, 256>>>(as1, ad1);
    agg_kernel<4><<<NN / 8, 256>>>(b1, bng, bnb, bnm, bnv, 4, 1, 0);

    // layer 2: GAT(256 -> 1x64)
    gemm3_kernel<64, 64, 128, 0, 5><<<dim3(1, 400), 128>>>(nullptr, W2, 64, 256);
    attn_kernel<1><<<NN / 8, 256>>>(as2, ad2);
    agg_kernel<1><<<NN / 8, 256>>>(b2, bng, bnb, bnm, bnv, 8, 0, 1);

    // pool + head
    pool_kernel<<<NN / 4, 256>>>(batch);
    head_kernel<<<GG, 64>>>(cw1, cb1, cw2, cb2, out);
}

// round 6
// speedup vs baseline: 1.3818x; 1.3818x over previous
#include <cuda_runtime.h>
#include <math.h>
#include <stdint.h>

// Problem constants
#define NN   25600          // nodes
#define EE   409600         // edges
#define GG   128            // graphs
#define INF_ 200            // raw feature dim
#define IN2  400            // 2*IN after nan-mask concat
#define HC4  256            // H*C for layers 0/1
#define ETOT (EE + NN)      // edges + self loops

#define NEG_BIG (-1.0e30f)  // finite "-inf" so online-softmax combine never does inf-inf

// ---------------- scratch (device globals; no allocation allowed) ----------------
__device__ __align__(16) float d_h   [(size_t)NN * HC4];     // GEMM output / attn input
__device__ __align__(16) float d_xn  [(size_t)NN * HC4];     // next-layer input
__device__ __align__(16) float d_o2  [(size_t)NN * 64];      // layer-2 node output
__device__ __align__(16) float d_asb[NN * 4];
__device__ __align__(16) float d_adb[NN * 4];
__device__ int   d_cnt[NN];
__device__ int   d_fill[NN];
__device__ float d_easum[NN];
__device__ int   d_rowptr[NN + 1];
__device__ int   d_csrc[ETOT];
__device__ float d_cea [ETOT];
__device__ float d_gsum[GG * 64];
__device__ float d_gcnt[GG];
__device__ float d_wd[9];   // we_dot: layer0 heads 0..3, layer1 heads 4..7, layer2 at 8

// ---------------- helpers ----------------
__device__ __forceinline__ float warp_sum(float v) {
    #pragma unroll
    for (int o = 16; o; o >>= 1) v += __shfl_xor_sync(0xffffffffu, v, o);
    return v;
}
// packed fp32x2 FMA (Blackwell FFMA2 — only reachable via PTX)
__device__ __forceinline__ void ffma2(uint64_t& d, uint64_t a, uint64_t b) {
    asm("fma.rn.f32x2 %0, %1, %2, %0;" : "+l"(d) : "l"(a), "l"(b));
}
__device__ __forceinline__ uint64_t dup2(float v) {
    uint64_t r; asm("mov.b64 %0, {%1, %1};" : "=l"(r) : "f"(v)); return r;
}
__device__ __forceinline__ float2 unpk(uint64_t v) {
    float2 r; asm("mov.b64 {%0, %1}, %2;" : "=f"(r.x), "=f"(r.y) : "l"(v)); return r;
}

// ---------------- zero scratch counters ----------------
__global__ void zero_kernel() {
    int i = blockIdx.x * blockDim.x + threadIdx.x;
    if (i < NN) { d_cnt[i] = 0; d_fill[i] = 0; d_easum[i] = 0.f; }
    if (i < GG * 64) d_gsum[i] = 0.f;
    if (i < GG) d_gcnt[i] = 0.f;
}

// ---------------- CSR build ----------------
__global__ void count_kernel(const int* __restrict__ ei, const float* __restrict__ ea) {
    int e = blockIdx.x * blockDim.x + threadIdx.x;
    if (e >= EE) return;
    int d = ei[EE + e];
    float v = ea[e];
    if (v != v) v = 0.f;              // nan_to_num
    atomicAdd(&d_cnt[d], 1);
    atomicAdd(&d_easum[d], v);
}

// single-block exclusive scan of (cnt[n]+1) -> rowptr, warp-shuffle based
__global__ void scan_kernel() {
    __shared__ int wsum[32];
    __shared__ int s_off;
    int tid = threadIdx.x, lane = tid & 31, wid = tid >> 5;
    if (tid == 0) { d_rowptr[0] = 0; s_off = 0; }
    __syncthreads();
    for (int base = 0; base < NN; base += 1024) {
        int v = d_cnt[base + tid] + 1;    // +1 for the self loop
        int inc = v;
        #pragma unroll
        for (int o = 1; o < 32; o <<= 1) {
            int t = __shfl_up_sync(0xffffffffu, inc, o);
            if (lane >= o) inc += t;
        }
        if (lane == 31) wsum[wid] = inc;
        __syncthreads();
        if (wid == 0) {
            int wi = wsum[lane];
            #pragma unroll
            for (int o = 1; o < 32; o <<= 1) {
                int t = __shfl_up_sync(0xffffffffu, wi, o);
                if (lane >= o) wi += t;
            }
            wsum[lane] = wi;              // inclusive warp sums
        }
        __syncthreads();
        int excl_w = wid ? wsum[wid - 1] : 0;
        d_rowptr[base + tid + 1] = s_off + excl_w + inc;
        __syncthreads();
        if (tid == 0) s_off += wsum[31];
        __syncthreads();
    }
}

__global__ void fill_kernel(const int* __restrict__ ei, const float* __restrict__ ea) {
    int e = blockIdx.x * blockDim.x + threadIdx.x;
    if (e >= EE) return;
    int s = ei[e], d = ei[EE + e];
    float v = ea[e];
    if (v != v) v = 0.f;
    int pos = d_rowptr[d] + atomicAdd(&d_fill[d], 1);
    d_csrc[pos] = s;
    d_cea[pos]  = v;
}

__global__ void selfloop_kernel() {
    int n = blockIdx.x * blockDim.x + threadIdx.x;
    if (n >= NN) return;
    int pos = d_rowptr[n + 1] - 1;    // self loop occupies the last slot of the row
    d_csrc[pos] = n;
    d_cea[pos]  = d_easum[n] / fmaxf((float)d_cnt[n], 1.f);
}

// ---------------- we_dot[h] = dot(We row of head h, ae[h]) ----------------
__global__ void wd_kernel(const float* We0, const float* ae0,
                          const float* We1, const float* ae1,
                          const float* We2, const float* ae2) {
    int w = threadIdx.x >> 5, lane = threadIdx.x & 31;
    if (w >= 9) return;
    const float *We, *ae; int h;
    if (w < 4)      { We = We0; ae = ae0; h = w; }
    else if (w < 8) { We = We1; ae = ae1; h = w - 4; }
    else            { We = We2; ae = ae2; h = 0; }
    float s = 0.f;
    for (int c = lane; c < 64; c += 32) s += We[h * 64 + c] * ae[h * 64 + c];
    s = warp_sum(s);
    if (lane == 0) d_wd[w] = s;
}

// ---------------- f32x2 GEMM (round-3 proven shape): d_h = A @ B ----------------
// XF=1: A synthesized from raw x: A[m,k] = k<200 ? nan2num(x[m,k]) : isnan(x[m,k-200]).
// Tile BM x BN, T threads, 8x8 per thread as 2x2 blocks of 4x4 across halves.
// B values duplicated into f32x2 via ALU MOVs (alu pipe is idle; smem wavefronts are not).
template <int BM, int BN, int T, int XF, int OCC>
__global__ __launch_bounds__(T, OCC) void gemm2_kernel(const float* __restrict__ Xin,
                                                       const float* __restrict__ B,
                                                       int Nn, int K) {
    const float* __restrict__ A = d_xn;
    constexpr int TX = BN / 8;          // threads across N
    constexpr int HM = BM / 2, HN = BN / 2;
    constexpr int AV = (BM * 4) / T;    // A float4 loads per thread per tile
    constexpr int BV = (BN * 4) / T;    // B float4 loads per thread per tile
    constexpr int BN4 = BN / 4;
    constexpr int BMP = BM + 4;         // pad, keeps 16B alignment of rows

    __shared__ __align__(16) float As[2][16][BMP];
    __shared__ __align__(16) float Bs[2][16][BN];

    int tid = threadIdx.x;
    int tx4 = (tid % TX) * 4;
    int ty4 = (tid / TX) * 4;
    int m0 = blockIdx.y * BM, n0 = blockIdx.x * BN;

    uint64_t acc[4][8];
    #pragma unroll
    for (int i = 0; i < 4; i++)
        #pragma unroll
        for (int j = 0; j < 8; j++) acc[i][j] = 0ull;

    float4 pa[AV], pb[BV];
    int arow[AV], ac[AV], brow[BV], bc[BV];
    #pragma unroll
    for (int i = 0; i < AV; i++) { int idx = tid + i * T; arow[i] = idx >> 2; ac[i] = idx & 3; }
    #pragma unroll
    for (int i = 0; i < BV; i++) { int idx = tid + i * T; brow[i] = idx / BN4; bc[i] = idx % BN4; }

    int ktiles = K >> 4;

    auto loadA = [&](int i, int k0) -> float4 {
        int m = m0 + arow[i];
        int kk = k0 + ac[i] * 4;
        if (XF) {
            int c = (kk < INF_) ? kk : (kk - INF_);
            float4 v = *(const float4*)&Xin[(size_t)m * INF_ + c];
            float4 r;
            bool lo = (kk < INF_);
            r.x = (v.x != v.x) ? (lo ? 0.f : 1.f) : (lo ? v.x : 0.f);
            r.y = (v.y != v.y) ? (lo ? 0.f : 1.f) : (lo ? v.y : 0.f);
            r.z = (v.z != v.z) ? (lo ? 0.f : 1.f) : (lo ? v.z : 0.f);
            r.w = (v.w != v.w) ? (lo ? 0.f : 1.f) : (lo ? v.w : 0.f);
            return r;
        } else {
            return *(const float4*)&A[(size_t)m * K + kk];
        }
    };
    auto storeTile = [&](int b) {
        #pragma unroll
        for (int i = 0; i < AV; i++) {
            As[b][ac[i] * 4 + 0][arow[i]] = pa[i].x;
            As[b][ac[i] * 4 + 1][arow[i]] = pa[i].y;
            As[b][ac[i] * 4 + 2][arow[i]] = pa[i].z;
            As[b][ac[i] * 4 + 3][arow[i]] = pa[i].w;
        }
        #pragma unroll
        for (int i = 0; i < BV; i++)
            *(float4*)&Bs[b][brow[i]][bc[i] * 4] = pb[i];
    };

    // preload tile 0
    #pragma unroll
    for (int i = 0; i < AV; i++) pa[i] = loadA(i, 0);
    #pragma unroll
    for (int i = 0; i < BV; i++)
        pb[i] = *(const float4*)&B[(size_t)brow[i] * Nn + n0 + bc[i] * 4];
    storeTile(0);
    __syncthreads();

    for (int t = 0; t < ktiles; t++) {
        int buf = t & 1;
        if (t + 1 < ktiles) {
            int k0 = (t + 1) << 4;
            #pragma unroll
            for (int i = 0; i < AV; i++) pa[i] = loadA(i, k0);
            #pragma unroll
            for (int i = 0; i < BV; i++)
                pb[i] = *(const float4*)&B[(size_t)(k0 + brow[i]) * Nn + n0 + bc[i] * 4];
        }
        const float (*Asb)[BMP] = As[buf];
        const float (*Bsb)[BN]  = Bs[buf];
        #pragma unroll
        for (int k = 0; k < 16; k++) {
            ulonglong2 aLo = *(const ulonglong2*)&Asb[k][ty4];
            ulonglong2 aHi = *(const ulonglong2*)&Asb[k][HM + ty4];
            float4 bLo = *(const float4*)&Bsb[k][tx4];
            float4 bHi = *(const float4*)&Bsb[k][HN + tx4];
            uint64_t a2[4] = {aLo.x, aLo.y, aHi.x, aHi.y};
            float bb[8] = {bLo.x, bLo.y, bLo.z, bLo.w, bHi.x, bHi.y, bHi.z, bHi.w};
            #pragma unroll
            for (int j = 0; j < 8; j++) {
                uint64_t bd = dup2(bb[j]);
                #pragma unroll
                for (int ii = 0; ii < 4; ii++) ffma2(acc[ii][j], a2[ii], bd);
            }
        }
        if (t + 1 < ktiles) storeTile(buf ^ 1);
        __syncthreads();
    }

    // epilogue: acc[ii][j] .lo/.hi = two consecutive M rows, col j
    #pragma unroll
    for (int ii = 0; ii < 4; ii++) {
        int rbase = (ii < 2) ? (ty4 + ii * 2) : (HM + ty4 + (ii - 2) * 2);
        float2 u[8];
        #pragma unroll
        for (int j = 0; j < 8; j++) u[j] = unpk(acc[ii][j]);
        size_t r0 = (size_t)(m0 + rbase) * Nn;
        size_t r1 = r0 + Nn;
        *(float4*)&d_h[r0 + n0 + tx4]      = make_float4(u[0].x, u[1].x, u[2].x, u[3].x);
        *(float4*)&d_h[r0 + n0 + HN + tx4] = make_float4(u[4].x, u[5].x, u[6].x, u[7].x);
        *(float4*)&d_h[r1 + n0 + tx4]      = make_float4(u[0].y, u[1].y, u[2].y, u[3].y);
        *(float4*)&d_h[r1 + n0 + HN + tx4] = make_float4(u[4].y, u[5].y, u[6].y, u[7].y);
    }
}

// ---------------- per-node attention scalars a_s, a_d (8 warps / block) ----------------
template <int H>
__global__ __launch_bounds__(256) void attn_kernel(const float* __restrict__ att_s,
                                                   const float* __restrict__ att_d) {
    constexpr int NPB = 8 / H;
    int tid = threadIdx.x, wid = tid >> 5, lane = tid & 31;
    int n = blockIdx.x * NPB + wid / H;
    int h = wid % H;
    const float2* hr  = (const float2*)(d_h + (size_t)n * (H * 64) + h * 64);
    const float2* asv = (const float2*)(att_s + h * 64);
    const float2* adv = (const float2*)(att_d + h * 64);
    float2 hv = hr[lane], sv = asv[lane], dv = adv[lane];
    float s  = hv.x * sv.x + hv.y * sv.y;
    float dd = hv.x * dv.x + hv.y * dv.y;
    s = warp_sum(s); dd = warp_sum(dd);
    if (lane == 0) { d_asb[n * H + h] = s; d_adb[n * H + h] = dd; }
}

// ---------------- segment softmax + aggregation: one warp per dst node ----------------
template <int H>
__global__ __launch_bounds__(256) void agg_kernel(const float* __restrict__ bias,
                           const float* __restrict__ bng, const float* __restrict__ bnb,
                           const float* __restrict__ bnm, const float* __restrict__ bnv,
                           int wd_off, int do_bn, int out_sel) {
    __shared__ int   s_src[8][32];
    __shared__ float s_wt[8][32][H];

    int gw = (blockIdx.x * blockDim.x + threadIdx.x) >> 5;
    if (gw >= NN) return;
    int lane = threadIdx.x & 31;
    int wwarp = threadIdx.x >> 5;
    int n = gw;
    int beg = d_rowptr[n], end = d_rowptr[n + 1];

    float adh[H], wdv[H];
    #pragma unroll
    for (int h = 0; h < H; h++) { adh[h] = d_adb[n * H + h]; wdv[h] = d_wd[wd_off + h]; }

    // single-pass online softmax statistics (max + sum), lane-strided.
    // mx starts at a finite NEG_BIG so the combine never computes (-inf) - (-inf).
    float mx[H], sm[H];
    #pragma unroll
    for (int h = 0; h < H; h++) { mx[h] = NEG_BIG; sm[h] = 0.f; }
    for (int e = beg + lane; e < end; e += 32) {
        int s = d_csrc[e]; float ev = d_cea[e];
        float av[H];
        if constexpr (H == 4) {
            float4 a4 = *(const float4*)&d_asb[s * 4];
            av[0] = a4.x; av[1] = a4.y; av[2] = a4.z; av[3] = a4.w;
        } else {
            av[0] = d_asb[s];
        }
        #pragma unroll
        for (int h = 0; h < H; h++) {
            float t = av[h] + adh[h] + ev * wdv[h];
            t = t > 0.f ? t : 0.2f * t;
            float mn = fmaxf(mx[h], t);
            sm[h] = sm[h] * __expf(mx[h] - mn) + __expf(t - mn);
            mx[h] = mn;
        }
    }
    // warp combine of (mx, sm) — all operands finite
    #pragma unroll
    for (int h = 0; h < H; h++) {
        #pragma unroll
        for (int o = 16; o; o >>= 1) {
            float mo = __shfl_xor_sync(0xffffffffu, mx[h], o);
            float so = __shfl_xor_sync(0xffffffffu, sm[h], o);
            float mn = fmaxf(mx[h], mo);
            sm[h] = sm[h] * __expf(mx[h] - mn) + so * __expf(mo - mn);
            mx[h] = mn;
        }
    }

    // gather pass: each lane owns PL consecutive channels
    constexpr int PL = (H * 64) / 32;     // 8 (H=4) or 2 (H=1)
    int hl = (lane * PL) >> 6;            // head of this lane's channels
    float acc[PL];
    #pragma unroll
    for (int j = 0; j < PL; j++) acc[j] = 0.f;

    for (int ec = beg; ec < end; ec += 32) {
        int e = ec + lane;
        if (e < end) {
            int s = d_csrc[e]; float ev = d_cea[e];
            s_src[wwarp][lane] = s;
            float av[H];
            if constexpr (H == 4) {
                float4 a4 = *(const float4*)&d_asb[s * 4];
                av[0] = a4.x; av[1] = a4.y; av[2] = a4.z; av[3] = a4.w;
            } else {
                av[0] = d_asb[s];
            }
            #pragma unroll
            for (int h = 0; h < H; h++) {
                float t = av[h] + adh[h] + ev * wdv[h];
                t = t > 0.f ? t : 0.2f * t;
                s_wt[wwarp][lane][h] = __expf(t - mx[h]);
            }
        }
        __syncwarp();
        int cnt = min(32, end - ec);
        #pragma unroll 4
        for (int i = 0; i < cnt; i++) {
            int s = s_src[wwarp][i];
            float w = s_wt[wwarp][i][hl];
            const float* hr = d_h + (size_t)s * (H * 64) + lane * PL;
            if constexpr (PL == 8) {
                float4 v0 = *(const float4*)hr;
                float4 v1 = *(const float4*)(hr + 4);
                acc[0] = fmaf(w, v0.x, acc[0]); acc[1] = fmaf(w, v0.y, acc[1]);
                acc[2] = fmaf(w, v0.z, acc[2]); acc[3] = fmaf(w, v0.w, acc[3]);
                acc[4] = fmaf(w, v1.x, acc[4]); acc[5] = fmaf(w, v1.y, acc[5]);
                acc[6] = fmaf(w, v1.z, acc[6]); acc[7] = fmaf(w, v1.w, acc[7]);
            } else {
                float2 v = *(const float2*)hr;
                acc[0] = fmaf(w, v.x, acc[0]);
                acc[1] = fmaf(w, v.y, acc[1]);
            }
        }
        __syncwarp();
    }

    float invl = 1.f / (sm[hl] + 1e-16f);
    float* ob = out_sel ? d_o2 : d_xn;
    #pragma unroll
    for (int j = 0; j < PL; j++) {
        int c = lane * PL + j;
        float v = acc[j] * invl + bias[c];
        if (do_bn) {
            v = (v - bnm[c]) * rsqrtf(bnv[c] + 1e-5f) * bng[c] + bnb[c];
            v = fmaxf(v, 0.f);
        }
        ob[(size_t)n * (H * 64) + c] = v;
    }
}

// ---------------- global mean pool accumulation ----------------
__global__ __launch_bounds__(256) void pool_kernel(const int* __restrict__ batch) {
    int t = blockIdx.x * blockDim.x + threadIdx.x;
    int n = t >> 6, c = t & 63;
    if (n >= NN) return;
    int b = batch[n];
    atomicAdd(&d_gsum[b * 64 + c], d_o2[(size_t)n * 64 + c]);
    if (c == 0) atomicAdd(&d_gcnt[b], 1.f);
}

// ---------------- MLP head: GELU(g@cw1+cb1)@cw2+cb2 ----------------
__global__ void head_kernel(const float* __restrict__ cw1, const float* __restrict__ cb1,
                            const float* __restrict__ cw2, const float* __restrict__ cb2,
                            float* __restrict__ out) {
    int g = blockIdx.x, j = threadIdx.x;   // 64 threads
    __shared__ float sg[64], sh[64];
    float cntv = fmaxf(d_gcnt[g], 1.f);
    sg[j] = d_gsum[g * 64 + j] / cntv;
    __syncthreads();
    float a = cb1[j];
    #pragma unroll
    for (int k = 0; k < 64; k++) a = fmaf(sg[k], cw1[k * 64 + j], a);
    sh[j] = 0.5f * a * (1.f + erff(a * 0.70710678118654752440f));   // exact GELU
    __syncthreads();
    if (j < 2) {
        float o = cb2[j];
        #pragma unroll
        for (int k = 0; k < 64; k++) o = fmaf(sh[k], cw2[k * 2 + j], o);
        out[g * 2 + j] = o;
    }
}

// ---------------- launch ----------------
extern "C" void kernel_launch(void* const* d_in, const int* in_sizes, int n_in,
                              void* d_out, int out_size) {
    (void)in_sizes; (void)n_in; (void)out_size;
    const float* x     = (const float*)d_in[0];
    const int*   ei    = (const int*)  d_in[1];
    const float* ea    = (const float*)d_in[2];
    const int*   batch = (const int*)  d_in[3];
    const float* W0  = (const float*)d_in[4];
    const float* as0 = (const float*)d_in[5];
    const float* ad0 = (const float*)d_in[6];
    const float* We0 = (const float*)d_in[7];
    const float* ae0 = (const float*)d_in[8];
    const float* b0  = (const float*)d_in[9];
    const float* W1  = (const float*)d_in[10];
    const float* as1 = (const float*)d_in[11];
    const float* ad1 = (const float*)d_in[12];
    const float* We1 = (const float*)d_in[13];
    const float* ae1 = (const float*)d_in[14];
    const float* b1  = (const float*)d_in[15];
    const float* W2  = (const float*)d_in[16];
    const float* as2 = (const float*)d_in[17];
    const float* ad2 = (const float*)d_in[18];
    const float* We2 = (const float*)d_in[19];
    const float* ae2 = (const float*)d_in[20];
    const float* b2  = (const float*)d_in[21];
    const float* bng = (const float*)d_in[22];
    const float* bnb = (const float*)d_in[23];
    const float* bnm = (const float*)d_in[24];
    const float* bnv = (const float*)d_in[25];
    const float* cw1 = (const float*)d_in[26];
    const float* cb1 = (const float*)d_in[27];
    const float* cw2 = (const float*)d_in[28];
    const float* cb2 = (const float*)d_in[29];
    float* out = (float*)d_out;

    // prep + layer-0 GEMM placed 4th so the ncu window lands on it
    zero_kernel<<<100, 256>>>();
    count_kernel<<<EE / 256, 256>>>(ei, ea);
    scan_kernel<<<1, 1024>>>();
    gemm2_kernel<128, 128, 256, 1, 2><<<dim3(2, 200), 256>>>(x, W0, 256, 400);  // layer 0 GEMM
    fill_kernel<<<EE / 256, 256>>>(ei, ea);
    selfloop_kernel<<<100, 256>>>();
    wd_kernel<<<1, 288>>>(We0, ae0, We1, ae1, We2, ae2);

    // layer 0: attention + aggregation + BN + ReLU
    attn_kernel<4><<<NN / 2, 256>>>(as0, ad0);
    agg_kernel<4><<<NN / 8, 256>>>(b0, bng, bnb, bnm, bnv, 0, 1, 0);

    // layer 1: GAT(256 -> 4x64) + BN + ReLU
    gemm2_kernel<128, 128, 256, 0, 2><<<dim3(2, 200), 256>>>(nullptr, W1, 256, 256);
    attn_kernel<4><<<NN / 2, 256>>>(as1, ad1);
    agg_kernel<4><<<NN / 8, 256>>>(b1, bng, bnb, bnm, bnv, 4, 1, 0);

    // layer 2: GAT(256 -> 1x64) — fine tiles, single wave
    gemm2_kernel<128, 64, 128, 0, 4><<<dim3(1, 200), 128>>>(nullptr, W2, 64, 256);
    attn_kernel<1><<<NN / 8, 256>>>(as2, ad2);
    agg_kernel<1><<<NN / 8, 256>>>(b2, bng, bnb, bnm, bnv, 8, 0, 1);

    // pool + head
    pool_kernel<<<NN / 4, 256>>>(batch);
    head_kernel<<<GG, 64>>>(cw1, cb1, cw2, cb2, out);
}

// round 8
// speedup vs baseline: 1.6308x; 1.1802x over previous
#include <cuda_runtime.h>
#include <cuda_bf16.h>
#include <math.h>
#include <stdint.h>

// Problem constants
#define NN   25600
#define EE   409600
#define GG   128
#define INF_ 200
#define HC4  256
#define ETOT (EE + NN)
#define KP0  448            // padded K for layer-0 GEMM (400 -> 448)

#define NEG_BIG (-1.0e30f)

// ---------------- scratch ----------------
__device__ __align__(16) float d_h   [(size_t)NN * HC4];
__device__ __align__(16) float d_o2  [(size_t)NN * 64];
__device__ __align__(16) __nv_bfloat16 d_xhi[(size_t)NN * HC4];
__device__ __align__(16) __nv_bfloat16 d_xlo[(size_t)NN * HC4];
__device__ __align__(16) __nv_bfloat16 d_a0hi[(size_t)NN * KP0];
__device__ __align__(16) __nv_bfloat16 d_a0lo[(size_t)NN * KP0];
__device__ __align__(16) __nv_bfloat16 d_b0hi[256 * KP0];
__device__ __align__(16) __nv_bfloat16 d_b0lo[256 * KP0];
__device__ __align__(16) __nv_bfloat16 d_b1hi[256 * 256];
__device__ __align__(16) __nv_bfloat16 d_b1lo[256 * 256];
__device__ __align__(16) __nv_bfloat16 d_b2hi[64 * 256];
__device__ __align__(16) __nv_bfloat16 d_b2lo[64 * 256];
__device__ __align__(16) float d_asb[NN * 4];
__device__ __align__(16) float d_adb[NN * 4];
__device__ int   d_cnt[NN];
__device__ int   d_fill[NN];
__device__ float d_easum[NN];
__device__ int   d_rowptr[NN + 1];
__device__ int   d_csrc[ETOT];
__device__ float d_cea [ETOT];
__device__ float d_gsum[GG * 64];
__device__ float d_gcnt[GG];
__device__ float d_wd[9];

// ---------------- helpers ----------------
__device__ __forceinline__ uint32_t smem_u32(const void* p) {
    uint32_t a;
    asm("{ .reg .u64 t; cvta.to.shared.u64 t, %1; cvt.u32.u64 %0, t; }" : "=r"(a) : "l"(p));
    return a;
}
__device__ __forceinline__ float warp_sum(float v) {
    #pragma unroll
    for (int o = 16; o; o >>= 1) v += __shfl_xor_sync(0xffffffffu, v, o);
    return v;
}
__device__ __forceinline__ void cp16(uint32_t smem, const void* g) {
    asm volatile("cp.async.cg.shared.global [%0], [%1], 16;" :: "r"(smem), "l"(g) : "memory");
}
__device__ __forceinline__ void ldsm4(uint32_t* r, uint32_t addr) {
    asm volatile("ldmatrix.sync.aligned.m8n8.x4.shared.b16 {%0,%1,%2,%3}, [%4];"
                 : "=r"(r[0]), "=r"(r[1]), "=r"(r[2]), "=r"(r[3]) : "r"(addr));
}
__device__ __forceinline__ void mma16816(float* d, const uint32_t* a, const uint32_t* b) {
    asm volatile("mma.sync.aligned.m16n8k16.row.col.f32.bf16.bf16.f32 "
                 "{%0,%1,%2,%3}, {%4,%5,%6,%7}, {%8,%9}, {%0,%1,%2,%3};"
                 : "+f"(d[0]), "+f"(d[1]), "+f"(d[2]), "+f"(d[3])
                 : "r"(a[0]), "r"(a[1]), "r"(a[2]), "r"(a[3]), "r"(b[0]), "r"(b[1]));
}

// ---------------- zero ----------------
__global__ void zero_kernel() {
    int i = blockIdx.x * blockDim.x + threadIdx.x;
    if (i < NN) { d_cnt[i] = 0; d_fill[i] = 0; d_easum[i] = 0.f; }
    if (i < GG * 64) d_gsum[i] = 0.f;
    if (i < GG) d_gcnt[i] = 0.f;
}

// ---------------- CSR build ----------------
__global__ void count_kernel(const int* __restrict__ ei, const float* __restrict__ ea) {
    int e = blockIdx.x * blockDim.x + threadIdx.x;
    if (e >= EE) return;
    int d = ei[EE + e];
    float v = ea[e];
    if (v != v) v = 0.f;
    atomicAdd(&d_cnt[d], 1);
    atomicAdd(&d_easum[d], v);
}

__global__ void scan_kernel() {
    __shared__ int wsum[32];
    __shared__ int s_off;
    int tid = threadIdx.x, lane = tid & 31, wid = tid >> 5;
    if (tid == 0) { d_rowptr[0] = 0; s_off = 0; }
    __syncthreads();
    for (int base = 0; base < NN; base += 1024) {
        int inc = d_cnt[base + tid] + 1;
        #pragma unroll
        for (int o = 1; o < 32; o <<= 1) {
            int t = __shfl_up_sync(0xffffffffu, inc, o);
            if (lane >= o) inc += t;
        }
        if (lane == 31) wsum[wid] = inc;
        __syncthreads();
        if (wid == 0) {
            int wi = wsum[lane];
            #pragma unroll
            for (int o = 1; o < 32; o <<= 1) {
                int t = __shfl_up_sync(0xffffffffu, wi, o);
                if (lane >= o) wi += t;
            }
            wsum[lane] = wi;
        }
        __syncthreads();
        int excl_w = wid ? wsum[wid - 1] : 0;
        d_rowptr[base + tid + 1] = s_off + excl_w + inc;
        __syncthreads();
        if (tid == 0) s_off += wsum[31];
        __syncthreads();
    }
}

__global__ void fill_kernel(const int* __restrict__ ei, const float* __restrict__ ea) {
    int e = blockIdx.x * blockDim.x + threadIdx.x;
    if (e >= EE) return;
    int s = ei[e], d = ei[EE + e];
    float v = ea[e];
    if (v != v) v = 0.f;
    int pos = d_rowptr[d] + atomicAdd(&d_fill[d], 1);
    d_csrc[pos] = s;
    d_cea[pos]  = v;
}

__global__ void selfloop_kernel() {
    int n = blockIdx.x * blockDim.x + threadIdx.x;
    if (n >= NN) return;
    int pos = d_rowptr[n + 1] - 1;
    d_csrc[pos] = n;
    d_cea[pos]  = d_easum[n] / fmaxf((float)d_cnt[n], 1.f);
}

// ---------------- we_dot ----------------
__global__ void wd_kernel(const float* We0, const float* ae0,
                          const float* We1, const float* ae1,
                          const float* We2, const float* ae2) {
    int w = threadIdx.x >> 5, lane = threadIdx.x & 31;
    if (w >= 9) return;
    const float *We, *ae; int h;
    if (w < 4)      { We = We0; ae = ae0; h = w; }
    else if (w < 8) { We = We1; ae = ae1; h = w - 4; }
    else            { We = We2; ae = ae2; h = 0; }
    float s = 0.f;
    for (int c = lane; c < 64; c += 32) s += We[h * 64 + c] * ae[h * 64 + c];
    s = warp_sum(s);
    if (lane == 0) d_wd[w] = s;
}

// ---------------- bf16 hi/lo split ----------------
__device__ __forceinline__ void split_bf16(float v, __nv_bfloat16& hi, __nv_bfloat16& lo) {
    hi = __float2bfloat16(v);
    lo = __float2bfloat16(v - __bfloat162float(hi));
}

// x[N,200] -> A0 hi/lo [N, 448]
__global__ void xsplit_kernel(const float* __restrict__ x) {
    int idx = blockIdx.x * blockDim.x + threadIdx.x;
    if (idx >= NN * KP0) return;
    int n = idx / KP0, kk = idx % KP0;
    float v = 0.f;
    if (kk < INF_) {
        float t = x[n * INF_ + kk];
        v = (t != t) ? 0.f : t;
    } else if (kk < 2 * INF_) {
        float t = x[n * INF_ + kk - INF_];
        v = (t != t) ? 1.f : 0.f;
    }
    __nv_bfloat16 h, l;
    split_bf16(v, h, l);
    d_a0hi[idx] = h; d_a0lo[idx] = l;
}

// W [K,N] row-major -> B hi/lo [N, Kpad]
__global__ void wsplit_kernel(const float* __restrict__ W, int K, int N, int Kpad, int sel) {
    int idx = blockIdx.x * blockDim.x + threadIdx.x;
    if (idx >= N * Kpad) return;
    int n = idx / Kpad, k = idx % Kpad;
    float v = (k < K) ? W[k * N + n] : 0.f;
    __nv_bfloat16 h, l;
    split_bf16(v, h, l);
    if (sel == 0)      { d_b0hi[idx] = h; d_b0lo[idx] = l; }
    else if (sel == 1) { d_b1hi[idx] = h; d_b1lo[idx] = l; }
    else               { d_b2hi[idx] = h; d_b2lo[idx] = l; }
}

// ---------------- HMMA bf16-split GEMM (mma.sync, sm_80-compatible PTX) ----------------
// C[M,NSTR](f32) = (Ahi+Alo) @ (Bhi+Blo)^T, 3-term split; block 128 x BN, 8 warps,
// warp tile 64 x (WN*8); K chunked by 64 into padded smem, cp.async double buffer.
template <int BN, int NSTR, int KPAD, int SEL>
__global__ __launch_bounds__(256, 1) void hmma_gemm() {
    constexpr int WM = 4;                 // m16 tiles per warp (64 rows)
    constexpr int WN = BN / 32;           // n8 tiles per warp (BN=128 -> 4, BN=64 -> 2)
    constexpr int PITCH = 144;            // smem row pitch bytes (64 bf16 + 16B pad)
    constexpr int ATILE = 128 * PITCH;
    constexpr int BTILE = BN * PITCH;
    constexpr int BUFSZ = 2 * ATILE + 2 * BTILE;
    constexpr int NCH = KPAD / 64;
    constexpr int ROWB = KPAD * 2;        // global row bytes

    const __nv_bfloat16* Ahi = (SEL == 0) ? d_a0hi : d_xhi;
    const __nv_bfloat16* Alo = (SEL == 0) ? d_a0lo : d_xlo;
    const __nv_bfloat16* Bhi = (SEL == 0) ? d_b0hi : (SEL == 1 ? d_b1hi : d_b2hi);
    const __nv_bfloat16* Blo = (SEL == 0) ? d_b0lo : (SEL == 1 ? d_b1lo : d_b2lo);

    extern __shared__ __align__(16) char dsm[];
    uint32_t sb = smem_u32(dsm);

    int tid = threadIdx.x, wid = tid >> 5, lane = tid & 31;
    int m0 = blockIdx.y * 128, n0 = blockIdx.x * BN;
    int mb = (wid >> 2) * 64;             // warp row offset in tile
    int nb = (wid & 3) * WN * 8;          // warp col offset in tile

    const char* gAh = (const char*)Ahi + (size_t)m0 * ROWB;
    const char* gAl = (const char*)Alo + (size_t)m0 * ROWB;
    const char* gBh = (const char*)Bhi + (size_t)n0 * ROWB;
    const char* gBl = (const char*)Blo + (size_t)n0 * ROWB;

    auto issue = [&](int c, int b) {
        uint32_t base = sb + b * BUFSZ;
        int cb = c * 128;
        for (int i = tid; i < 1024; i += 256) {
            int r = i >> 3, u = (i & 7) * 16;
            uint32_t off = r * PITCH + u;
            size_t g = (size_t)r * ROWB + cb + u;
            cp16(base + off,         gAh + g);
            cp16(base + ATILE + off, gAl + g);
        }
        for (int i = tid; i < BN * 8; i += 256) {
            int r = i >> 3, u = (i & 7) * 16;
            uint32_t off = r * PITCH + u;
            size_t g = (size_t)r * ROWB + cb + u;
            cp16(base + 2 * ATILE + off,         gBh + g);
            cp16(base + 2 * ATILE + BTILE + off, gBl + g);
        }
        asm volatile("cp.async.commit_group;" ::: "memory");
    };

    float acc[WM][WN][4];
    #pragma unroll
    for (int i = 0; i < WM; i++)
        #pragma unroll
        for (int j = 0; j < WN; j++)
            #pragma unroll
            for (int q = 0; q < 4; q++) acc[i][j][q] = 0.f;

    issue(0, 0);
    for (int c = 0; c < NCH; c++) {
        int buf = c & 1;
        if (c + 1 < NCH) {
            issue(c + 1, buf ^ 1);
            asm volatile("cp.async.wait_group 1;" ::: "memory");
        } else {
            asm volatile("cp.async.wait_group 0;" ::: "memory");
        }
        __syncthreads();

        uint32_t base  = sb + buf * BUFSZ;
        uint32_t a_row = base + mb * PITCH;
        uint32_t b_row = base + 2 * ATILE + nb * PITCH;
        uint32_t a_ln  = (lane & 15) * PITCH + (lane >> 4) * 16;
        uint32_t b_ln  = ((lane & 7) + ((lane >> 4) << 3)) * PITCH + ((lane >> 3) & 1) * 16;

        #pragma unroll
        for (int ks = 0; ks < 4; ks++) {
            uint32_t ah[WM][4], al[WM][4], bh[WN / 2][4], bl[WN / 2][4];
            uint32_t ao = ks * 32 + a_ln;
            #pragma unroll
            for (int mt = 0; mt < WM; mt++) {
                ldsm4(ah[mt], a_row + mt * 16 * PITCH + ao);
                ldsm4(al[mt], a_row + ATILE + mt * 16 * PITCH + ao);
            }
            uint32_t bo = ks * 32 + b_ln;
            #pragma unroll
            for (int nt2 = 0; nt2 < WN / 2; nt2++) {
                ldsm4(bh[nt2], b_row + nt2 * 16 * PITCH + bo);
                ldsm4(bl[nt2], b_row + BTILE + nt2 * 16 * PITCH + bo);
            }
            #pragma unroll
            for (int mt = 0; mt < WM; mt++)
                #pragma unroll
                for (int nt = 0; nt < WN; nt++) {
                    const uint32_t* bhp = &bh[nt >> 1][(nt & 1) * 2];
                    const uint32_t* blp = &bl[nt >> 1][(nt & 1) * 2];
                    mma16816(acc[mt][nt], ah[mt], bhp);
                    mma16816(acc[mt][nt], al[mt], bhp);
                    mma16816(acc[mt][nt], ah[mt], blp);
                }
        }
        __syncthreads();
    }

    // epilogue: C fragment -> d_h
    int r0 = m0 + mb + (lane >> 2);
    int c0 = n0 + nb + (lane & 3) * 2;
    #pragma unroll
    for (int mt = 0; mt < WM; mt++)
        #pragma unroll
        for (int nt = 0; nt < WN; nt++) {
            int rr = r0 + mt * 16, cc = c0 + nt * 8;
            *(float2*)&d_h[(size_t)rr * NSTR + cc]       = make_float2(acc[mt][nt][0], acc[mt][nt][1]);
            *(float2*)&d_h[(size_t)(rr + 8) * NSTR + cc] = make_float2(acc[mt][nt][2], acc[mt][nt][3]);
        }
}

// ---------------- per-node attention scalars ----------------
template <int H>
__global__ __launch_bounds__(256) void attn_kernel(const float* __restrict__ att_s,
                                                   const float* __restrict__ att_d) {
    constexpr int NPB = 8 / H;
    int tid = threadIdx.x, wid = tid >> 5, lane = tid & 31;
    int n = blockIdx.x * NPB + wid / H;
    int h = wid % H;
    const float2* hr  = (const float2*)(d_h + (size_t)n * (H * 64) + h * 64);
    const float2* asv = (const float2*)(att_s + h * 64);
    const float2* adv = (const float2*)(att_d + h * 64);
    float2 hv = hr[lane], sv = asv[lane], dv = adv[lane];
    float s  = hv.x * sv.x + hv.y * sv.y;
    float dd = hv.x * dv.x + hv.y * dv.y;
    s = warp_sum(s); dd = warp_sum(dd);
    if (lane == 0) { d_asb[n * H + h] = s; d_adb[n * H + h] = dd; }
}

// ---------------- segment softmax + aggregation ----------------
// out_mode 0: write bf16 hi/lo to d_xhi/d_xlo; 1: fp32 to d_o2.
template <int H>
__global__ __launch_bounds__(256) void agg_kernel(const float* __restrict__ bias,
                           const float* __restrict__ bng, const float* __restrict__ bnb,
                           const float* __restrict__ bnm, const float* __restrict__ bnv,
                           int wd_off, int do_bn, int out_mode) {
    __shared__ int   s_src[8][32];
    __shared__ float s_wt[8][32][H];

    int gw = (blockIdx.x * blockDim.x + threadIdx.x) >> 5;
    if (gw >= NN) return;
    int lane = threadIdx.x & 31;
    int wwarp = threadIdx.x >> 5;
    int n = gw;
    int beg = d_rowptr[n], end = d_rowptr[n + 1];

    float adh[H], wdv[H];
    #pragma unroll
    for (int h = 0; h < H; h++) { adh[h] = d_adb[n * H + h]; wdv[h] = d_wd[wd_off + h]; }

    float mx[H], sm[H];
    #pragma unroll
    for (int h = 0; h < H; h++) { mx[h] = NEG_BIG; sm[h] = 0.f; }
    for (int e = beg + lane; e < end; e += 32) {
        int s = d_csrc[e]; float ev = d_cea[e];
        float av[H];
        if constexpr (H == 4) {
            float4 a4 = *(const float4*)&d_asb[s * 4];
            av[0] = a4.x; av[1] = a4.y; av[2] = a4.z; av[3] = a4.w;
        } else {
            av[0] = d_asb[s];
        }
        #pragma unroll
        for (int h = 0; h < H; h++) {
            float t = av[h] + adh[h] + ev * wdv[h];
            t = t > 0.f ? t : 0.2f * t;
            float mn = fmaxf(mx[h], t);
            sm[h] = sm[h] * __expf(mx[h] - mn) + __expf(t - mn);
            mx[h] = mn;
        }
    }
    #pragma unroll
    for (int h = 0; h < H; h++) {
        #pragma unroll
        for (int o = 16; o; o >>= 1) {
            float mo = __shfl_xor_sync(0xffffffffu, mx[h], o);
            float so = __shfl_xor_sync(0xffffffffu, sm[h], o);
            float mn = fmaxf(mx[h], mo);
            sm[h] = sm[h] * __expf(mx[h] - mn) + so * __expf(mo - mn);
            mx[h] = mn;
        }
    }

    constexpr int PL = (H * 64) / 32;
    int hl = (lane * PL) >> 6;
    float acc[PL];
    #pragma unroll
    for (int j = 0; j < PL; j++) acc[j] = 0.f;

    for (int ec = beg; ec < end; ec += 32) {
        int e = ec + lane;
        if (e < end) {
            int s = d_csrc[e]; float ev = d_cea[e];
            s_src[wwarp][lane] = s;
            float av[H];
            if constexpr (H == 4) {
                float4 a4 = *(const float4*)&d_asb[s * 4];
                av[0] = a4.x; av[1] = a4.y; av[2] = a4.z; av[3] = a4.w;
            } else {
                av[0] = d_asb[s];
            }
            #pragma unroll
            for (int h = 0; h < H; h++) {
                float t = av[h] + adh[h] + ev * wdv[h];
                t = t > 0.f ? t : 0.2f * t;
                s_wt[wwarp][lane][h] = __expf(t - mx[h]);
            }
        }
        __syncwarp();
        int cnt = min(32, end - ec);
        #pragma unroll 4
        for (int i = 0; i < cnt; i++) {
            int s = s_src[wwarp][i];
            float w = s_wt[wwarp][i][hl];
            const float* hr = d_h + (size_t)s * (H * 64) + lane * PL;
            if constexpr (PL == 8) {
                float4 v0 = *(const float4*)hr;
                float4 v1 = *(const float4*)(hr + 4);
                acc[0] = fmaf(w, v0.x, acc[0]); acc[1] = fmaf(w, v0.y, acc[1]);
                acc[2] = fmaf(w, v0.z, acc[2]); acc[3] = fmaf(w, v0.w, acc[3]);
                acc[4] = fmaf(w, v1.x, acc[4]); acc[5] = fmaf(w, v1.y, acc[5]);
                acc[6] = fmaf(w, v1.z, acc[6]); acc[7] = fmaf(w, v1.w, acc[7]);
            } else {
                float2 v = *(const float2*)hr;
                acc[0] = fmaf(w, v.x, acc[0]);
                acc[1] = fmaf(w, v.y, acc[1]);
            }
        }
        __syncwarp();
    }

    float invl = 1.f / (sm[hl] + 1e-16f);
    #pragma unroll
    for (int j = 0; j < PL; j++) {
        int c = lane * PL + j;
        float v = acc[j] * invl + bias[c];
        if (do_bn) {
            v = (v - bnm[c]) * rsqrtf(bnv[c] + 1e-5f) * bng[c] + bnb[c];
            v = fmaxf(v, 0.f);
        }
        if (out_mode == 0) {
            __nv_bfloat16 h16, l16;
            split_bf16(v, h16, l16);
            d_xhi[(size_t)n * 256 + c] = h16;
            d_xlo[(size_t)n * 256 + c] = l16;
        } else {
            d_o2[(size_t)n * 64 + c] = v;
        }
    }
}

// ---------------- pool + head ----------------
__global__ __launch_bounds__(256) void pool_kernel(const int* __restrict__ batch) {
    int t = blockIdx.x * blockDim.x + threadIdx.x;
    int n = t >> 6, c = t & 63;
    if (n >= NN) return;
    int b = batch[n];
    atomicAdd(&d_gsum[b * 64 + c], d_o2[(size_t)n * 64 + c]);
    if (c == 0) atomicAdd(&d_gcnt[b], 1.f);
}

__global__ void head_kernel(const float* __restrict__ cw1, const float* __restrict__ cb1,
                            const float* __restrict__ cw2, const float* __restrict__ cb2,
                            float* __restrict__ out) {
    int g = blockIdx.x, j = threadIdx.x;
    __shared__ float sg[64], sh[64];
    float cntv = fmaxf(d_gcnt[g], 1.f);
    sg[j] = d_gsum[g * 64 + j] / cntv;
    __syncthreads();
    float a = cb1[j];
    #pragma unroll
    for (int k = 0; k < 64; k++) a = fmaf(sg[k], cw1[k * 64 + j], a);
    sh[j] = 0.5f * a * (1.f + erff(a * 0.70710678118654752440f));
    __syncthreads();
    if (j < 2) {
        float o = cb2[j];
        #pragma unroll
        for (int k = 0; k < 64; k++) o = fmaf(sh[k], cw2[k * 2 + j], o);
        out[g * 2 + j] = o;
    }
}

// ---------------- launch ----------------
extern "C" void kernel_launch(void* const* d_in, const int* in_sizes, int n_in,
                              void* d_out, int out_size) {
    (void)in_sizes; (void)n_in; (void)out_size;
    const float* x     = (const float*)d_in[0];
    const int*   ei    = (const int*)  d_in[1];
    const float* ea    = (const float*)d_in[2];
    const int*   batch = (const int*)  d_in[3];
    const float* W0  = (const float*)d_in[4];
    const float* as0 = (const float*)d_in[5];
    const float* ad0 = (const float*)d_in[6];
    const float* We0 = (const float*)d_in[7];
    const float* ae0 = (const float*)d_in[8];
    const float* b0  = (const float*)d_in[9];
    const float* W1  = (const float*)d_in[10];
    const float* as1 = (const float*)d_in[11];
    const float* ad1 = (const float*)d_in[12];
    const float* We1 = (const float*)d_in[13];
    const float* ae1 = (const float*)d_in[14];
    const float* b1  = (const float*)d_in[15];
    const float* W2  = (const float*)d_in[16];
    const float* as2 = (const float*)d_in[17];
    const float* ad2 = (const float*)d_in[18];
    const float* We2 = (const float*)d_in[19];
    const float* ae2 = (const float*)d_in[20];
    const float* b2  = (const float*)d_in[21];
    const float* bng = (const float*)d_in[22];
    const float* bnb = (const float*)d_in[23];
    const float* bnm = (const float*)d_in[24];
    const float* bnv = (const float*)d_in[25];
    const float* cw1 = (const float*)d_in[26];
    const float* cb1 = (const float*)d_in[27];
    const float* cw2 = (const float*)d_in[28];
    const float* cb2 = (const float*)d_in[29];
    float* out = (float*)d_out;

    // dynamic smem: double-buffered chunk = 2*(2*ATILE + 2*BTILE)
    const int SMEM_G01 = 2 * (2 * 128 * 144 + 2 * 128 * 144);   // 147456
    const int SMEM_G2  = 2 * (2 * 128 * 144 + 2 * 64 * 144);    // 110592
    cudaFuncSetAttribute(hmma_gemm<128, 256, KP0, 0>, cudaFuncAttributeMaxDynamicSharedMemorySize, SMEM_G01);
    cudaFuncSetAttribute(hmma_gemm<128, 256, 256, 1>, cudaFuncAttributeMaxDynamicSharedMemorySize, SMEM_G01);
    cudaFuncSetAttribute(hmma_gemm<64, 64, 256, 2>,   cudaFuncAttributeMaxDynamicSharedMemorySize, SMEM_G2);

    // order: gemm0 is the 4th launch so the ncu window lands on it
    zero_kernel<<<100, 256>>>();
    xsplit_kernel<<<(NN * KP0 + 255) / 256, 256>>>(x);
    wsplit_kernel<<<(256 * KP0 + 255) / 256, 256>>>(W0, 400, 256, KP0, 0);
    hmma_gemm<128, 256, KP0, 0><<<dim3(2, 200), 256, SMEM_G01>>>();      // layer-0 GEMM
    wsplit_kernel<<<(256 * 256 + 255) / 256, 256>>>(W1, 256, 256, 256, 1);
    wsplit_kernel<<<(64 * 256 + 255) / 256, 256>>>(W2, 256, 64, 256, 2);
    count_kernel<<<EE / 256, 256>>>(ei, ea);
    scan_kernel<<<1, 1024>>>();
    fill_kernel<<<EE / 256, 256>>>(ei, ea);
    selfloop_kernel<<<100, 256>>>();
    wd_kernel<<<1, 288>>>(We0, ae0, We1, ae1, We2, ae2);

    // layer 0
    attn_kernel<4><<<NN / 2, 256>>>(as0, ad0);
    agg_kernel<4><<<NN / 8, 256>>>(b0, bng, bnb, bnm, bnv, 0, 1, 0);

    // layer 1
    hmma_gemm<128, 256, 256, 1><<<dim3(2, 200), 256, SMEM_G01>>>();
    attn_kernel<4><<<NN / 2, 256>>>(as1, ad1);
    agg_kernel<4><<<NN / 8, 256>>>(b1, bng, bnb, bnm, bnv, 4, 1, 0);

    // layer 2
    hmma_gemm<64, 64, 256, 2><<<dim3(1, 200), 256, SMEM_G2>>>();
    attn_kernel<1><<<NN / 8, 256>>>(as2, ad2);
    agg_kernel<1><<<NN / 8, 256>>>(b2, bng, bnb, bnm, bnv, 8, 0, 1);

    // pool + head
    pool_kernel<<<NN / 4, 256>>>(batch);
    head_kernel<<<GG, 64>>>(cw1, cb1, cw2, cb2, out);
}